// round 14
// baseline (speedup 1.0000x reference)
#include <cuda_runtime.h>
#include <cuda_bf16.h>
#include <stdint.h>

#define DMODEL 1024
#define NHEADS 16
#define DKK    64
#define SEQ    2048
#define NBATCH 2
#define NTOK   (NBATCH*SEQ)   // 4096
#define WELEM  (DMODEL*DMODEL)

// ---------------- scratch (allocation-free rule: __device__ globals) --------
__device__ __nv_bfloat16 g_Xhi[NTOK*DMODEL], g_Xlo[NTOK*DMODEL];
__device__ __nv_bfloat16 g_Whi[4*WELEM],     g_Wlo[4*WELEM];     // q,k,v,o
__device__ __nv_bfloat16 g_Qhi[NTOK*DMODEL], g_Qlo[NTOK*DMODEL]; // head-major
__device__ __nv_bfloat16 g_Khi[NTOK*DMODEL], g_Klo[NTOK*DMODEL];
__device__ __nv_bfloat16 g_Vhi[NTOK*DMODEL], g_Vlo[NTOK*DMODEL];
__device__ __nv_bfloat16 g_Chi[NTOK*DMODEL], g_Clo[NTOK*DMODEL]; // context

// ---------------- HMMA helpers (sm_80+ PTX, valid on plain compute_103) -----
__device__ __forceinline__ uint32_t smem_to_u32(const void* p) {
    uint32_t a;
    asm("{ .reg .u64 t; cvta.to.shared.u64 t, %1; cvt.u32.u64 %0, t; }" : "=r"(a) : "l"(p));
    return a;
}
__device__ __forceinline__ void ldsm4(uint32_t& r0, uint32_t& r1, uint32_t& r2,
                                      uint32_t& r3, uint32_t addr) {
    asm volatile("ldmatrix.sync.aligned.m8n8.x4.shared.b16 {%0,%1,%2,%3}, [%4];"
                 : "=r"(r0), "=r"(r1), "=r"(r2), "=r"(r3) : "r"(addr));
}
__device__ __forceinline__ void ldsm4t(uint32_t& r0, uint32_t& r1, uint32_t& r2,
                                       uint32_t& r3, uint32_t addr) {
    asm volatile("ldmatrix.sync.aligned.m8n8.x4.trans.shared.b16 {%0,%1,%2,%3}, [%4];"
                 : "=r"(r0), "=r"(r1), "=r"(r2), "=r"(r3) : "r"(addr));
}
__device__ __forceinline__ void mma16816(float* d, const uint32_t* a, const uint32_t* b) {
    asm volatile("mma.sync.aligned.m16n8k16.row.col.f32.bf16.bf16.f32 "
                 "{%0,%1,%2,%3}, {%4,%5,%6,%7}, {%8,%9}, {%0,%1,%2,%3};"
                 : "+f"(d[0]), "+f"(d[1]), "+f"(d[2]), "+f"(d[3])
                 : "r"(a[0]), "r"(a[1]), "r"(a[2]), "r"(a[3]), "r"(b[0]), "r"(b[1]));
}
__device__ __forceinline__ void cpa16(uint32_t saddr, const void* g) {
    asm volatile("cp.async.cg.shared.global [%0], [%1], 16;" :: "r"(saddr), "l"(g));
}
#define CPA_COMMIT() asm volatile("cp.async.commit_group;" ::: "memory")
// split two floats into packed bf16 hi pair + lo pair
__device__ __forceinline__ void split2(float a, float b, uint32_t& hi, uint32_t& lo) {
    __nv_bfloat16 ah = __float2bfloat16(a), bh = __float2bfloat16(b);
    __nv_bfloat16 al = __float2bfloat16(a - __bfloat162float(ah));
    __nv_bfloat16 bl = __float2bfloat16(b - __bfloat162float(bh));
    hi = ((uint32_t)__bfloat16_as_ushort(bh) << 16) | (uint32_t)__bfloat16_as_ushort(ah);
    lo = ((uint32_t)__bfloat16_as_ushort(bl) << 16) | (uint32_t)__bfloat16_as_ushort(al);
}

// ---------------- GEMM smem layout (double-buffered, KCHUNK=32) -------------
#define KCHUNK    32
#define NCHUNKS   (DMODEL / KCHUNK)  // 32
#define TROWB_G   80                 // 64B data + 16B pad -> conflict-free ldsm
#define TILE_G    (128*TROWB_G)      // 10240
#define STAGE_G   (4*TILE_G)         // 40960: [Ahi][Alo][Bhi][Blo]
#define SM_TOTAL_G (2*STAGE_G)       // 81920

// ---------------- flash smem layout (single stage, 144B stride) -------------
#define TROWB     144
#define SQ_HI     0
#define SQ_LO     18432
#define SK_HI_F   36864
#define SK_LO_F   46080
#define SV_HI_F   55296
#define SV_LO_F   64512
#define FSMEM     73728

// ---------------------------------------------------------------------------
// Kernel 0: fp32 -> bf16 hi/lo split of X and the 4 weights.
// ---------------------------------------------------------------------------
__global__ void __launch_bounds__(256)
cvt_kernel(const float* __restrict__ x,
           const float* __restrict__ wq, const float* __restrict__ wk,
           const float* __restrict__ wv, const float* __restrict__ wo)
{
    int y = blockIdx.y;
    const float* src;
    __nv_bfloat16 *dh, *dl;
    int n4;
    if (y == 0) { src = x; dh = g_Xhi; dl = g_Xlo; n4 = NTOK*DMODEL/4; }
    else {
        src = (y == 1) ? wq : (y == 2) ? wk : (y == 3) ? wv : wo;
        size_t off = (size_t)(y - 1) * WELEM;
        dh = g_Whi + off; dl = g_Wlo + off; n4 = WELEM/4;
    }
    int i = blockIdx.x * blockDim.x + threadIdx.x;
    if (i >= n4) return;
    float4 v = reinterpret_cast<const float4*>(src)[i];
    uint32_t h0, l0, h1, l1;
    split2(v.x, v.y, h0, l0);
    split2(v.z, v.w, h1, l1);
    uint2 uh; uh.x = h0; uh.y = h1;
    uint2 ul; ul.x = l0; ul.y = l1;
    *reinterpret_cast<uint2*>(dh + 4*(size_t)i) = uh;
    *reinterpret_cast<uint2*>(dl + 4*(size_t)i) = ul;
}

// ---------------------------------------------------------------------------
// HMMA mainloop, 512 threads, warp tile 32x32, cp.async double-buffered.
// acc[2][4][4] = A[row0:+128][1024] @ B[col0:+128][1024]^T (3-term bf16 split)
// ---------------------------------------------------------------------------
__device__ __forceinline__ void gemm_issue(
    uint32_t soff, size_t ga, size_t gb, uint32_t sb, int st, int k0,
    const __nv_bfloat16* Ahi, const __nv_bfloat16* Alo,
    const __nv_bfloat16* Bhi, const __nv_bfloat16* Blo)
{
    uint32_t base = sb + (uint32_t)st * STAGE_G;
    cpa16(base +            soff, Ahi + ga + k0);
    cpa16(base + TILE_G   + soff, Alo + ga + k0);
    cpa16(base + 2*TILE_G + soff, Bhi + gb + k0);
    cpa16(base + 3*TILE_G + soff, Blo + gb + k0);
    CPA_COMMIT();
}

__device__ __forceinline__ void gemm_compute(
    uint32_t sb, int st, int wm, int wn, uint32_t lrow, uint32_t lhalf,
    float acc[2][4][4])
{
    const uint32_t base = sb + (uint32_t)st * STAGE_G;
#pragma unroll
    for (int ks = 0; ks < 2; ks++) {
        const uint32_t kb = ks * 32;
        uint32_t bhf[4][2], blf[4][2];
#pragma unroll
        for (int half = 0; half < 2; half++) {
            uint32_t r0, r1, r2, r3;
            uint32_t baddr = base + 2*TILE_G +
                (uint32_t)(wn * 32 + half * 16 + lrow) * TROWB_G + kb + lhalf;
            ldsm4(r0, r1, r2, r3, baddr);
            bhf[half*2+0][0] = r0; bhf[half*2+0][1] = r2;
            bhf[half*2+1][0] = r1; bhf[half*2+1][1] = r3;
            ldsm4(r0, r1, r2, r3, baddr + TILE_G);
            blf[half*2+0][0] = r0; blf[half*2+0][1] = r2;
            blf[half*2+1][0] = r1; blf[half*2+1][1] = r3;
        }
        uint32_t af[2][4];
#pragma unroll
        for (int mi = 0; mi < 2; mi++) {
            uint32_t aaddr = base +
                (uint32_t)(wm * 32 + mi * 16 + lrow) * TROWB_G + kb + lhalf;
            ldsm4(af[mi][0], af[mi][1], af[mi][2], af[mi][3], aaddr);
        }
        // pass 1: hi*hi (8 independent MMAs)
#pragma unroll
        for (int mi = 0; mi < 2; mi++)
#pragma unroll
            for (int ni = 0; ni < 4; ni++) mma16816(acc[mi][ni], af[mi], bhf[ni]);
        // pass 2: hi*lo
#pragma unroll
        for (int mi = 0; mi < 2; mi++)
#pragma unroll
            for (int ni = 0; ni < 4; ni++) mma16816(acc[mi][ni], af[mi], blf[ni]);
        // A lo fragments (reuse regs), pass 3: lo*hi
#pragma unroll
        for (int mi = 0; mi < 2; mi++) {
            uint32_t aaddr = base + TILE_G +
                (uint32_t)(wm * 32 + mi * 16 + lrow) * TROWB_G + kb + lhalf;
            ldsm4(af[mi][0], af[mi][1], af[mi][2], af[mi][3], aaddr);
        }
#pragma unroll
        for (int mi = 0; mi < 2; mi++)
#pragma unroll
            for (int ni = 0; ni < 4; ni++) mma16816(acc[mi][ni], af[mi], bhf[ni]);
    }
}

__device__ __forceinline__ void gemm_mainloop_mma(
    const __nv_bfloat16* __restrict__ Ahi, const __nv_bfloat16* __restrict__ Alo,
    const __nv_bfloat16* __restrict__ Bhi, const __nv_bfloat16* __restrict__ Blo,
    int row0, int col0, uint32_t sb, float acc[2][4][4])
{
    const int tid  = threadIdx.x;
    const int lane = tid & 31;
    const int wid  = tid >> 5;           // 0..15
    const int wm   = wid & 3;            // 4 warps in M (32 rows each)
    const int wn   = wid >> 2;           // 4 warps in N (32 cols each)
    const uint32_t lrow  = (uint32_t)(lane & 15);
    const uint32_t lhalf = (uint32_t)((lane >> 4) * 16);

    // cp.async geometry: 1 x 16B chunk per tile per thread (512 thr = 8KB/tile)
    const int rr  = tid >> 2;            // 0..127
    const int c16 = tid & 3;             // 16B chunk within 64B row
    const uint32_t soff = (uint32_t)(rr * TROWB_G + c16 * 16);
    const size_t ga = (size_t)(row0 + rr) * DMODEL + c16 * 8;
    const size_t gb = (size_t)(col0 + rr) * DMODEL + c16 * 8;

#pragma unroll
    for (int mi = 0; mi < 2; mi++)
#pragma unroll
        for (int ni = 0; ni < 4; ni++)
#pragma unroll
            for (int e = 0; e < 4; e++) acc[mi][ni][e] = 0.f;

    gemm_issue(soff, ga, gb, sb, 0, 0,      Ahi, Alo, Bhi, Blo);
    gemm_issue(soff, ga, gb, sb, 1, KCHUNK, Ahi, Alo, Bhi, Blo);

    for (int kc = 0; kc < NCHUNKS; kc++) {
        if (kc + 1 < NCHUNKS) asm volatile("cp.async.wait_group 1;" ::: "memory");
        else                  asm volatile("cp.async.wait_group 0;" ::: "memory");
        __syncthreads();
        gemm_compute(sb, kc & 1, wm, wn, lrow, lhalf, acc);
        __syncthreads();
        if (kc + 2 < NCHUNKS)
            gemm_issue(soff, ga, gb, sb, kc & 1, (kc + 2) * KCHUNK, Ahi, Alo, Bhi, Blo);
    }
}

// ---------------------------------------------------------------------------
// Kernel 1: QKV projection; epilogue stores head-major bf16 hi/lo.
// ---------------------------------------------------------------------------
__global__ void __launch_bounds__(512, 2)
qkv_mma_kernel()
{
    extern __shared__ char smem[];
    uint32_t sb = smem_to_u32(smem);

    const int z = blockIdx.z;
    const int row0 = blockIdx.x * 128;
    const int col0 = blockIdx.y * 128;

    float acc[2][4][4];
    gemm_mainloop_mma(g_Xhi, g_Xlo, g_Whi + (size_t)z * WELEM, g_Wlo + (size_t)z * WELEM,
                      row0, col0, sb, acc);

    const float scale = (z == 0) ? 0.125f : 1.0f;   // 1/sqrt(64) folded into Q
    __nv_bfloat16* Ohi = (z == 0) ? g_Qhi : (z == 1) ? g_Khi : g_Vhi;
    __nv_bfloat16* Olo = (z == 0) ? g_Qlo : (z == 1) ? g_Klo : g_Vlo;

    const int lane = threadIdx.x & 31;
    const int wid  = threadIdx.x >> 5;
    const int wm = wid & 3, wn = wid >> 2;
    const int lr = lane >> 2;
    const int lc = (lane & 3) * 2;

#pragma unroll
    for (int mi = 0; mi < 2; mi++)
#pragma unroll
        for (int ni = 0; ni < 4; ni++) {
            int c = col0 + wn * 32 + ni * 8 + lc;
            int h = c >> 6, d = c & 63;
#pragma unroll
            for (int half = 0; half < 2; half++) {
                int t = row0 + wm * 32 + mi * 16 + lr + half * 8;
                int b = t >> 11, s = t & 2047;
                uint32_t hi, lo;
                split2(acc[mi][ni][half*2] * scale, acc[mi][ni][half*2+1] * scale, hi, lo);
                size_t o = (((size_t)(b * NHEADS + h)) * SEQ + s) * DKK + d;
                *reinterpret_cast<uint32_t*>(Ohi + o) = hi;
                *reinterpret_cast<uint32_t*>(Olo + o) = lo;
            }
        }
}

// ---------------------------------------------------------------------------
// Kernel 3: output projection  out = C @ Wo^T + bo
// ---------------------------------------------------------------------------
__global__ void __launch_bounds__(512, 2)
outproj_mma_kernel(const float* __restrict__ bo, float* __restrict__ out)
{
    extern __shared__ char smem[];
    uint32_t sb = smem_to_u32(smem);

    const int row0 = blockIdx.x * 128;
    const int col0 = blockIdx.y * 128;

    float acc[2][4][4];
    gemm_mainloop_mma(g_Chi, g_Clo, g_Whi + (size_t)3 * WELEM, g_Wlo + (size_t)3 * WELEM,
                      row0, col0, sb, acc);

    const int lane = threadIdx.x & 31;
    const int wid  = threadIdx.x >> 5;
    const int wm = wid & 3, wn = wid >> 2;
    const int lr = lane >> 2;
    const int lc = (lane & 3) * 2;

#pragma unroll
    for (int mi = 0; mi < 2; mi++)
#pragma unroll
        for (int ni = 0; ni < 4; ni++) {
            int c = col0 + wn * 32 + ni * 8 + lc;
            float2 bb = *reinterpret_cast<const float2*>(bo + c);
#pragma unroll
            for (int half = 0; half < 2; half++) {
                int t = row0 + wm * 32 + mi * 16 + lr + half * 8;
                float2 v;
                v.x = acc[mi][ni][half*2 + 0] + bb.x;
                v.y = acc[mi][ni][half*2 + 1] + bb.y;
                *reinterpret_cast<float2*>(out + (size_t)t * DMODEL + c) = v;
            }
        }
}

// ---------------------------------------------------------------------------
// Kernel 2: flash attention on HMMA (bf16 hi/lo 3-term). Proven R7 version.
// ---------------------------------------------------------------------------
__global__ void __launch_bounds__(256, 2)
flash_mma_kernel()
{
    extern __shared__ char smem[];
    uint32_t sb = smem_to_u32(smem);
    const int tid  = threadIdx.x;
    const int lane = tid & 31;
    const int wq   = tid >> 5;
    const int bh   = blockIdx.y;
    const int qb   = blockIdx.x;
    const int b    = bh >> 4, h = bh & 15;

    const uint32_t lrow  = (uint32_t)(lane & 15);
    const uint32_t lhalf = (uint32_t)((lane >> 4) * 16);
    const uint32_t vrow  = (uint32_t)((lane & 7) + ((lane >> 4) & 1) * 8);
    const uint32_t vcol  = (uint32_t)(((lane >> 3) & 1) * 8);

    const size_t qoff  = ((size_t)bh * SEQ + (size_t)qb * 128) * DKK;
    const size_t kvoff = (size_t)bh * SEQ * DKK;

#pragma unroll
    for (int i = 0; i < 4; i++) {
        int idx = tid + i * 256;
        int rr = idx >> 3, c16 = idx & 7;
        int so = rr * TROWB + c16 * 16;
        size_t g = qoff + (size_t)rr * DKK + c16 * 8;
        *reinterpret_cast<uint4*>(smem + SQ_HI + so) = *reinterpret_cast<const uint4*>(g_Qhi + g);
        *reinterpret_cast<uint4*>(smem + SQ_LO + so) = *reinterpret_cast<const uint4*>(g_Qlo + g);
    }

    float s[8][4];
    float c[8][4];
    float mA = -1e30f, mB = -1e30f, lA = 0.f, lB = 0.f;
#pragma unroll
    for (int di = 0; di < 8; di++)
#pragma unroll
        for (int e = 0; e < 4; e++) c[di][e] = 0.f;

    for (int kt = 0; kt < SEQ / 64; kt++) {
        __syncthreads();
        const size_t kb0 = kvoff + (size_t)kt * 64 * DKK;
#pragma unroll
        for (int i = 0; i < 2; i++) {
            int idx = tid + i * 256;
            int rr = idx >> 3, c16 = idx & 7;
            int so = rr * TROWB + c16 * 16;
            size_t g = kb0 + (size_t)rr * DKK + c16 * 8;
            *reinterpret_cast<uint4*>(smem + SK_HI_F + so) = *reinterpret_cast<const uint4*>(g_Khi + g);
            *reinterpret_cast<uint4*>(smem + SK_LO_F + so) = *reinterpret_cast<const uint4*>(g_Klo + g);
            *reinterpret_cast<uint4*>(smem + SV_HI_F + so) = *reinterpret_cast<const uint4*>(g_Vhi + g);
            *reinterpret_cast<uint4*>(smem + SV_LO_F + so) = *reinterpret_cast<const uint4*>(g_Vlo + g);
        }
        __syncthreads();

        // ---- S = Q K^T ----
#pragma unroll
        for (int ni = 0; ni < 8; ni++)
#pragma unroll
            for (int e = 0; e < 4; e++) s[ni][e] = 0.f;

#pragma unroll
        for (int ks = 0; ks < 4; ks++) {
            const uint32_t kb = ks * 32;
            uint32_t ah[4], al[4];
            uint32_t qaddr = sb + SQ_HI + (uint32_t)(wq * 16 + lrow) * TROWB + kb + lhalf;
            ldsm4(ah[0], ah[1], ah[2], ah[3], qaddr);
            ldsm4(al[0], al[1], al[2], al[3], qaddr + (SQ_LO - SQ_HI));
#pragma unroll
            for (int g = 0; g < 4; g++) {
                uint32_t r0, r1, r2, r3;
                uint32_t kaddr = sb + SK_HI_F + (uint32_t)(g * 16 + lrow) * TROWB + kb + lhalf;
                ldsm4(r0, r1, r2, r3, kaddr);
                uint32_t bh0[2] = {r0, r2}, bh1[2] = {r1, r3};
                ldsm4(r0, r1, r2, r3, kaddr + (SK_LO_F - SK_HI_F));
                uint32_t bl0[2] = {r0, r2}, bl1[2] = {r1, r3};
                mma16816(s[2*g],   ah, bh0); mma16816(s[2*g+1], ah, bh1);
                mma16816(s[2*g],   ah, bl0); mma16816(s[2*g+1], ah, bl1);
                mma16816(s[2*g],   al, bh0); mma16816(s[2*g+1], al, bh1);
            }
        }

        // ---- online softmax ----
        float cA = s[0][0], cB = s[0][2];
#pragma unroll
        for (int ni = 0; ni < 8; ni++) {
            cA = fmaxf(cA, fmaxf(s[ni][0], s[ni][1]));
            cB = fmaxf(cB, fmaxf(s[ni][2], s[ni][3]));
        }
#pragma unroll
        for (int off = 1; off <= 2; off <<= 1) {
            cA = fmaxf(cA, __shfl_xor_sync(0xffffffffu, cA, off));
            cB = fmaxf(cB, __shfl_xor_sync(0xffffffffu, cB, off));
        }
        float nA = fmaxf(mA, cA), nB = fmaxf(mB, cB);
        float scA = __expf(mA - nA), scB = __expf(mB - nB);
        mA = nA; mB = nB;
        float lsA = 0.f, lsB = 0.f;
#pragma unroll
        for (int ni = 0; ni < 8; ni++) {
            s[ni][0] = __expf(s[ni][0] - mA); lsA += s[ni][0];
            s[ni][1] = __expf(s[ni][1] - mA); lsA += s[ni][1];
            s[ni][2] = __expf(s[ni][2] - mB); lsB += s[ni][2];
            s[ni][3] = __expf(s[ni][3] - mB); lsB += s[ni][3];
        }
#pragma unroll
        for (int off = 1; off <= 2; off <<= 1) {
            lsA += __shfl_xor_sync(0xffffffffu, lsA, off);
            lsB += __shfl_xor_sync(0xffffffffu, lsB, off);
        }
        lA = lA * scA + lsA;
        lB = lB * scB + lsB;
#pragma unroll
        for (int di = 0; di < 8; di++) {
            c[di][0] *= scA; c[di][1] *= scA;
            c[di][2] *= scB; c[di][3] *= scB;
        }

        // ---- O += P V ----
#pragma unroll
        for (int ks = 0; ks < 4; ks++) {
            uint32_t pa_hi[4], pa_lo[4];
            split2(s[2*ks][0],   s[2*ks][1],   pa_hi[0], pa_lo[0]);
            split2(s[2*ks][2],   s[2*ks][3],   pa_hi[1], pa_lo[1]);
            split2(s[2*ks+1][0], s[2*ks+1][1], pa_hi[2], pa_lo[2]);
            split2(s[2*ks+1][2], s[2*ks+1][3], pa_hi[3], pa_lo[3]);
#pragma unroll
            for (int g = 0; g < 4; g++) {
                uint32_t r0, r1, r2, r3;
                uint32_t vaddr = sb + SV_HI_F + (uint32_t)(ks * 16 + vrow) * TROWB
                               + (uint32_t)(g * 16 + vcol) * 2;
                ldsm4t(r0, r1, r2, r3, vaddr);
                uint32_t vh0[2] = {r0, r2}, vh1[2] = {r1, r3};
                ldsm4t(r0, r1, r2, r3, vaddr + (SV_LO_F - SV_HI_F));
                uint32_t vl0[2] = {r0, r2}, vl1[2] = {r1, r3};
                mma16816(c[2*g],   pa_hi, vh0); mma16816(c[2*g+1], pa_hi, vh1);
                mma16816(c[2*g],   pa_hi, vl0); mma16816(c[2*g+1], pa_hi, vl1);
                mma16816(c[2*g],   pa_lo, vh0); mma16816(c[2*g+1], pa_lo, vh1);
            }
        }
    }

    // ---- epilogue ----
    const float iA = 1.f / lA, iB = 1.f / lB;
    const int srowA = qb * 128 + wq * 16 + (lane >> 2);
    const size_t baseA = ((size_t)(b * SEQ + srowA)) * DMODEL + h * DKK + (lane & 3) * 2;
    const size_t baseB = baseA + (size_t)8 * DMODEL;
#pragma unroll
    for (int di = 0; di < 8; di++) {
        uint32_t hi, lo;
        split2(c[di][0] * iA, c[di][1] * iA, hi, lo);
        *reinterpret_cast<uint32_t*>(g_Chi + baseA + di * 8) = hi;
        *reinterpret_cast<uint32_t*>(g_Clo + baseA + di * 8) = lo;
        split2(c[di][2] * iB, c[di][3] * iB, hi, lo);
        *reinterpret_cast<uint32_t*>(g_Chi + baseB + di * 8) = hi;
        *reinterpret_cast<uint32_t*>(g_Clo + baseB + di * 8) = lo;
    }
}

// ---------------------------------------------------------------------------
extern "C" void kernel_launch(void* const* d_in, const int* in_sizes, int n_in,
                              void* d_out, int out_size)
{
    (void)in_sizes; (void)n_in; (void)out_size;
    const float* x  = (const float*)d_in[0];
    const float* wq = (const float*)d_in[1];
    const float* wk = (const float*)d_in[2];
    const float* wv = (const float*)d_in[3];
    const float* wo = (const float*)d_in[4];
    const float* bo = (const float*)d_in[5];
    float* out = (float*)d_out;

    cudaFuncSetAttribute(qkv_mma_kernel,     cudaFuncAttributeMaxDynamicSharedMemorySize, SM_TOTAL_G);
    cudaFuncSetAttribute(outproj_mma_kernel, cudaFuncAttributeMaxDynamicSharedMemorySize, SM_TOTAL_G);
    cudaFuncSetAttribute(flash_mma_kernel,   cudaFuncAttributeMaxDynamicSharedMemorySize, FSMEM);

    // 0) split-convert X and all weights to bf16 hi/lo
    cvt_kernel<<<dim3(4096, 5), 256>>>(x, wq, wk, wv, wo);

    // 1) QKV projections (HMMA, 512 threads, 32x32 warp tiles)
    qkv_mma_kernel<<<dim3(NTOK / 128, DMODEL / 128, 3), 512, SM_TOTAL_G>>>();

    // 2) flash attention (HMMA)
    flash_mma_kernel<<<dim3(SEQ / 128, NBATCH * NHEADS), 256, FSMEM>>>();

    // 3) output projection (HMMA, 512 threads) + bias
    outproj_mma_kernel<<<dim3(NTOK / 128, DMODEL / 128), 512, SM_TOTAL_G>>>(bo, out);
}

// round 15
// speedup vs baseline: 1.2341x; 1.2341x over previous
#include <cuda_runtime.h>
#include <cuda_bf16.h>
#include <cuda_fp16.h>
#include <stdint.h>

#define DMODEL 1024
#define NHEADS 16
#define DKK    64
#define SEQ    2048
#define NBATCH 2
#define NTOK   (NBATCH*SEQ)   // 4096
#define WELEM  (DMODEL*DMODEL)

// ---------------- scratch (allocation-free rule: __device__ globals) --------
__device__ __half        g_Xhi[NTOK*DMODEL], g_Xlo[NTOK*DMODEL];  // fp16 2-term
__device__ __half        g_W[4*WELEM];                            // fp16 single (q,k,v,o)
__device__ __nv_bfloat16 g_Qhi[NTOK*DMODEL], g_Qlo[NTOK*DMODEL];  // bf16 (flash)
__device__ __nv_bfloat16 g_Khi[NTOK*DMODEL], g_Klo[NTOK*DMODEL];
__device__ __nv_bfloat16 g_Vhi[NTOK*DMODEL], g_Vlo[NTOK*DMODEL];
__device__ __half        g_Chi[NTOK*DMODEL], g_Clo[NTOK*DMODEL];  // fp16 2-term

// ---------------- HMMA helpers (sm_80+ PTX, valid on plain compute_103) -----
__device__ __forceinline__ uint32_t smem_to_u32(const void* p) {
    uint32_t a;
    asm("{ .reg .u64 t; cvta.to.shared.u64 t, %1; cvt.u32.u64 %0, t; }" : "=r"(a) : "l"(p));
    return a;
}
__device__ __forceinline__ void ldsm4(uint32_t& r0, uint32_t& r1, uint32_t& r2,
                                      uint32_t& r3, uint32_t addr) {
    asm volatile("ldmatrix.sync.aligned.m8n8.x4.shared.b16 {%0,%1,%2,%3}, [%4];"
                 : "=r"(r0), "=r"(r1), "=r"(r2), "=r"(r3) : "r"(addr));
}
__device__ __forceinline__ void ldsm4t(uint32_t& r0, uint32_t& r1, uint32_t& r2,
                                       uint32_t& r3, uint32_t addr) {
    asm volatile("ldmatrix.sync.aligned.m8n8.x4.trans.shared.b16 {%0,%1,%2,%3}, [%4];"
                 : "=r"(r0), "=r"(r1), "=r"(r2), "=r"(r3) : "r"(addr));
}
// bf16 mma (flash)
__device__ __forceinline__ void mma16816(float* d, const uint32_t* a, const uint32_t* b) {
    asm volatile("mma.sync.aligned.m16n8k16.row.col.f32.bf16.bf16.f32 "
                 "{%0,%1,%2,%3}, {%4,%5,%6,%7}, {%8,%9}, {%0,%1,%2,%3};"
                 : "+f"(d[0]), "+f"(d[1]), "+f"(d[2]), "+f"(d[3])
                 : "r"(a[0]), "r"(a[1]), "r"(a[2]), "r"(a[3]), "r"(b[0]), "r"(b[1]));
}
// fp16 mma (projections)
__device__ __forceinline__ void mma16816h(float* d, const uint32_t* a, const uint32_t* b) {
    asm volatile("mma.sync.aligned.m16n8k16.row.col.f32.f16.f16.f32 "
                 "{%0,%1,%2,%3}, {%4,%5,%6,%7}, {%8,%9}, {%0,%1,%2,%3};"
                 : "+f"(d[0]), "+f"(d[1]), "+f"(d[2]), "+f"(d[3])
                 : "r"(a[0]), "r"(a[1]), "r"(a[2]), "r"(a[3]), "r"(b[0]), "r"(b[1]));
}
// split two floats into packed bf16 hi pair + lo pair
__device__ __forceinline__ void split2(float a, float b, uint32_t& hi, uint32_t& lo) {
    __nv_bfloat16 ah = __float2bfloat16(a), bh = __float2bfloat16(b);
    __nv_bfloat16 al = __float2bfloat16(a - __bfloat162float(ah));
    __nv_bfloat16 bl = __float2bfloat16(b - __bfloat162float(bh));
    hi = ((uint32_t)__bfloat16_as_ushort(bh) << 16) | (uint32_t)__bfloat16_as_ushort(ah);
    lo = ((uint32_t)__bfloat16_as_ushort(bl) << 16) | (uint32_t)__bfloat16_as_ushort(al);
}
// split two floats into packed fp16 hi pair + lo pair
__device__ __forceinline__ void split2h(float a, float b, uint32_t& hi, uint32_t& lo) {
    __half ah = __float2half_rn(a), bh = __float2half_rn(b);
    __half al = __float2half_rn(a - __half2float(ah));
    __half bl = __float2half_rn(b - __half2float(bh));
    hi = ((uint32_t)__half_as_ushort(bh) << 16) | (uint32_t)__half_as_ushort(ah);
    lo = ((uint32_t)__half_as_ushort(bl) << 16) | (uint32_t)__half_as_ushort(al);
}

// ---------------- GEMM smem layout (R8 style, fp16 3 tiles) -----------------
#define TROWB     144                // 128B data + 16B pad, conflict-free ldsm
#define TILE_B    (128*TROWB)        // 18432
#define SA_HI     0
#define SA_LO     (TILE_B)
#define SB        (2*TILE_B)
#define SM_TOTAL_G (3*TILE_B)        // 55296
#define KCHUNK    64
#define NCHUNKS   (DMODEL / KCHUNK)  // 16

// ---------------- flash smem layout (unchanged, bf16) -----------------------
#define SQ_HI     0
#define SQ_LO     18432
#define SK_HI_F   36864
#define SK_LO_F   46080
#define SV_HI_F   55296
#define SV_LO_F   64512
#define FSMEM     73728

// ---------------------------------------------------------------------------
// Kernel 0: X -> fp16 hi/lo split; weights -> single fp16.
// ---------------------------------------------------------------------------
__global__ void __launch_bounds__(256)
cvt_kernel(const float* __restrict__ x,
           const float* __restrict__ wq, const float* __restrict__ wk,
           const float* __restrict__ wv, const float* __restrict__ wo)
{
    int y = blockIdx.y;
    int i = blockIdx.x * blockDim.x + threadIdx.x;
    if (y == 0) {
        if (i >= NTOK*DMODEL/4) return;
        float4 v = reinterpret_cast<const float4*>(x)[i];
        uint32_t h0, l0, h1, l1;
        split2h(v.x, v.y, h0, l0);
        split2h(v.z, v.w, h1, l1);
        uint2 uh; uh.x = h0; uh.y = h1;
        uint2 ul; ul.x = l0; ul.y = l1;
        *reinterpret_cast<uint2*>(g_Xhi + 4*(size_t)i) = uh;
        *reinterpret_cast<uint2*>(g_Xlo + 4*(size_t)i) = ul;
    } else {
        if (i >= WELEM/4) return;
        const float* src = (y == 1) ? wq : (y == 2) ? wk : (y == 3) ? wv : wo;
        __half* dst = g_W + (size_t)(y - 1) * WELEM;
        float4 v = reinterpret_cast<const float4*>(src)[i];
        uint2 u;
        u.x = ((uint32_t)__half_as_ushort(__float2half_rn(v.y)) << 16)
            |  (uint32_t)__half_as_ushort(__float2half_rn(v.x));
        u.y = ((uint32_t)__half_as_ushort(__float2half_rn(v.w)) << 16)
            |  (uint32_t)__half_as_ushort(__float2half_rn(v.z));
        *reinterpret_cast<uint2*>(dst + 4*(size_t)i) = u;
    }
}

// ---------------------------------------------------------------------------
// fp16 2-term HMMA mainloop (R8 structure): acc = (Ah+Al) @ B^T
// 256 threads, warp tile 64x32 (2 warps M x 4 warps N), KCHUNK=64.
// ---------------------------------------------------------------------------
__device__ __forceinline__ void gemm_mainloop_fp16(
    const __half* __restrict__ Ahi, const __half* __restrict__ Alo,
    const __half* __restrict__ B,
    int row0, int col0, char* smem, uint32_t smem_base,
    float acc[4][4][4])
{
    const int tid  = threadIdx.x;
    const int lane = tid & 31;
    const int wid  = tid >> 5;
    const int wm   = wid & 1;
    const int wn   = wid >> 1;

    int so[4];
    size_t ga[4], gb[4];
#pragma unroll
    for (int i = 0; i < 4; i++) {
        int idx = tid + i * 256;
        int rr  = idx >> 3;              // 0..127
        int c16 = idx & 7;               // 16B chunk (8 fp16)
        so[i] = rr * TROWB + c16 * 16;
        ga[i] = (size_t)(row0 + rr) * DMODEL + c16 * 8;
        gb[i] = (size_t)(col0 + rr) * DMODEL + c16 * 8;
    }

    const uint32_t lrow  = (uint32_t)(lane & 15);
    const uint32_t lhalf = (uint32_t)((lane >> 4) * 16);

#pragma unroll
    for (int mi = 0; mi < 4; mi++)
#pragma unroll
        for (int ni = 0; ni < 4; ni++)
#pragma unroll
            for (int e = 0; e < 4; e++) acc[mi][ni][e] = 0.f;

    for (int kc = 0; kc < NCHUNKS; kc++) {
        const int k0 = kc * KCHUNK;
        uint4 vah[4], val[4], vb[4];
#pragma unroll
        for (int i = 0; i < 4; i++) {
            vah[i] = *reinterpret_cast<const uint4*>(Ahi + ga[i] + k0);
            val[i] = *reinterpret_cast<const uint4*>(Alo + ga[i] + k0);
            vb[i]  = *reinterpret_cast<const uint4*>(B   + gb[i] + k0);
        }
        __syncthreads();   // previous iteration's compute done
#pragma unroll
        for (int i = 0; i < 4; i++) {
            *reinterpret_cast<uint4*>(smem + SA_HI + so[i]) = vah[i];
            *reinterpret_cast<uint4*>(smem + SA_LO + so[i]) = val[i];
            *reinterpret_cast<uint4*>(smem + SB    + so[i]) = vb[i];
        }
        __syncthreads();

#pragma unroll
        for (int ks = 0; ks < 4; ks++) {        // 4 x k16 per chunk
            const uint32_t kb = ks * 32;

            uint32_t bf[4][2];
#pragma unroll
            for (int half = 0; half < 2; half++) {
                uint32_t r0, r1, r2, r3;
                uint32_t baddr = smem_base + SB +
                    (uint32_t)(wn * 32 + half * 16 + lrow) * TROWB + kb + lhalf;
                ldsm4(r0, r1, r2, r3, baddr);
                bf[half*2+0][0] = r0; bf[half*2+0][1] = r2;
                bf[half*2+1][0] = r1; bf[half*2+1][1] = r3;
            }

            uint32_t af[4][4];
#pragma unroll
            for (int mi = 0; mi < 4; mi++) {
                uint32_t aaddr = smem_base + SA_HI +
                    (uint32_t)(wm * 64 + mi * 16 + lrow) * TROWB + kb + lhalf;
                ldsm4(af[mi][0], af[mi][1], af[mi][2], af[mi][3], aaddr);
            }
#pragma unroll
            for (int mi = 0; mi < 4; mi++)
#pragma unroll
                for (int ni = 0; ni < 4; ni++)
                    mma16816h(acc[mi][ni], af[mi], bf[ni]);

#pragma unroll
            for (int mi = 0; mi < 4; mi++) {
                uint32_t aaddr = smem_base + SA_LO +
                    (uint32_t)(wm * 64 + mi * 16 + lrow) * TROWB + kb + lhalf;
                ldsm4(af[mi][0], af[mi][1], af[mi][2], af[mi][3], aaddr);
            }
#pragma unroll
            for (int mi = 0; mi < 4; mi++)
#pragma unroll
                for (int ni = 0; ni < 4; ni++)
                    mma16816h(acc[mi][ni], af[mi], bf[ni]);
        }
    }
}

// ---------------------------------------------------------------------------
// Kernel 1: QKV projection (fp16 2-term); epilogue stores head-major bf16 hi/lo.
// ---------------------------------------------------------------------------
__global__ void __launch_bounds__(256, 2)
qkv_mma_kernel()
{
    extern __shared__ char smem[];
    uint32_t smem_base = smem_to_u32(smem);

    const int z = blockIdx.z;
    const int row0 = blockIdx.x * 128;
    const int col0 = blockIdx.y * 128;

    float acc[4][4][4];
    gemm_mainloop_fp16(g_Xhi, g_Xlo, g_W + (size_t)z * WELEM,
                       row0, col0, smem, smem_base, acc);

    const float scale = (z == 0) ? 0.125f : 1.0f;   // 1/sqrt(64) folded into Q
    __nv_bfloat16* Ohi = (z == 0) ? g_Qhi : (z == 1) ? g_Khi : g_Vhi;
    __nv_bfloat16* Olo = (z == 0) ? g_Qlo : (z == 1) ? g_Klo : g_Vlo;

    const int lane = threadIdx.x & 31;
    const int wid  = threadIdx.x >> 5;
    const int wm = wid & 1, wn = wid >> 1;
    const int lr = lane >> 2;
    const int lc = (lane & 3) * 2;

#pragma unroll
    for (int mi = 0; mi < 4; mi++)
#pragma unroll
        for (int ni = 0; ni < 4; ni++) {
            int c = col0 + wn * 32 + ni * 8 + lc;
            int h = c >> 6, d = c & 63;
#pragma unroll
            for (int half = 0; half < 2; half++) {
                int t = row0 + wm * 64 + mi * 16 + lr + half * 8;
                int b = t >> 11, s = t & 2047;
                uint32_t hi, lo;
                split2(acc[mi][ni][half*2] * scale, acc[mi][ni][half*2+1] * scale, hi, lo);
                size_t o = (((size_t)(b * NHEADS + h)) * SEQ + s) * DKK + d;
                *reinterpret_cast<uint32_t*>(Ohi + o) = hi;
                *reinterpret_cast<uint32_t*>(Olo + o) = lo;
            }
        }
}

// ---------------------------------------------------------------------------
// Kernel 3: output projection  out = C @ Wo^T + bo  (fp16 2-term)
// ---------------------------------------------------------------------------
__global__ void __launch_bounds__(256, 2)
outproj_mma_kernel(const float* __restrict__ bo, float* __restrict__ out)
{
    extern __shared__ char smem[];
    uint32_t smem_base = smem_to_u32(smem);

    const int row0 = blockIdx.x * 128;
    const int col0 = blockIdx.y * 128;

    float acc[4][4][4];
    gemm_mainloop_fp16(g_Chi, g_Clo, g_W + (size_t)3 * WELEM,
                       row0, col0, smem, smem_base, acc);

    const int lane = threadIdx.x & 31;
    const int wid  = threadIdx.x >> 5;
    const int wm = wid & 1, wn = wid >> 1;
    const int lr = lane >> 2;
    const int lc = (lane & 3) * 2;

#pragma unroll
    for (int mi = 0; mi < 4; mi++)
#pragma unroll
        for (int ni = 0; ni < 4; ni++) {
            int c = col0 + wn * 32 + ni * 8 + lc;
            float2 bb = *reinterpret_cast<const float2*>(bo + c);
#pragma unroll
            for (int half = 0; half < 2; half++) {
                int t = row0 + wm * 64 + mi * 16 + lr + half * 8;
                float2 v;
                v.x = acc[mi][ni][half*2 + 0] + bb.x;
                v.y = acc[mi][ni][half*2 + 1] + bb.y;
                *reinterpret_cast<float2*>(out + (size_t)t * DMODEL + c) = v;
            }
        }
}

// ---------------------------------------------------------------------------
// Kernel 2: flash attention on HMMA (bf16 hi/lo 3-term). Proven R8 version;
// only the epilogue changes: context now stored as fp16 hi/lo.
// ---------------------------------------------------------------------------
__global__ void __launch_bounds__(256, 2)
flash_mma_kernel()
{
    extern __shared__ char smem[];
    uint32_t sb = smem_to_u32(smem);
    const int tid  = threadIdx.x;
    const int lane = tid & 31;
    const int wq   = tid >> 5;
    const int bh   = blockIdx.y;
    const int qb   = blockIdx.x;
    const int b    = bh >> 4, h = bh & 15;

    const uint32_t lrow  = (uint32_t)(lane & 15);
    const uint32_t lhalf = (uint32_t)((lane >> 4) * 16);
    const uint32_t vrow  = (uint32_t)((lane & 7) + ((lane >> 4) & 1) * 8);
    const uint32_t vcol  = (uint32_t)(((lane >> 3) & 1) * 8);

    const size_t qoff  = ((size_t)bh * SEQ + (size_t)qb * 128) * DKK;
    const size_t kvoff = (size_t)bh * SEQ * DKK;

#pragma unroll
    for (int i = 0; i < 4; i++) {
        int idx = tid + i * 256;
        int rr = idx >> 3, c16 = idx & 7;
        int so = rr * TROWB + c16 * 16;
        size_t g = qoff + (size_t)rr * DKK + c16 * 8;
        *reinterpret_cast<uint4*>(smem + SQ_HI + so) = *reinterpret_cast<const uint4*>(g_Qhi + g);
        *reinterpret_cast<uint4*>(smem + SQ_LO + so) = *reinterpret_cast<const uint4*>(g_Qlo + g);
    }

    float s[8][4];
    float c[8][4];
    float mA = -1e30f, mB = -1e30f, lA = 0.f, lB = 0.f;
#pragma unroll
    for (int di = 0; di < 8; di++)
#pragma unroll
        for (int e = 0; e < 4; e++) c[di][e] = 0.f;

    for (int kt = 0; kt < SEQ / 64; kt++) {
        __syncthreads();
        const size_t kb0 = kvoff + (size_t)kt * 64 * DKK;
#pragma unroll
        for (int i = 0; i < 2; i++) {
            int idx = tid + i * 256;
            int rr = idx >> 3, c16 = idx & 7;
            int so = rr * TROWB + c16 * 16;
            size_t g = kb0 + (size_t)rr * DKK + c16 * 8;
            *reinterpret_cast<uint4*>(smem + SK_HI_F + so) = *reinterpret_cast<const uint4*>(g_Khi + g);
            *reinterpret_cast<uint4*>(smem + SK_LO_F + so) = *reinterpret_cast<const uint4*>(g_Klo + g);
            *reinterpret_cast<uint4*>(smem + SV_HI_F + so) = *reinterpret_cast<const uint4*>(g_Vhi + g);
            *reinterpret_cast<uint4*>(smem + SV_LO_F + so) = *reinterpret_cast<const uint4*>(g_Vlo + g);
        }
        __syncthreads();

        // ---- S = Q K^T ----
#pragma unroll
        for (int ni = 0; ni < 8; ni++)
#pragma unroll
            for (int e = 0; e < 4; e++) s[ni][e] = 0.f;

#pragma unroll
        for (int ks = 0; ks < 4; ks++) {
            const uint32_t kb = ks * 32;
            uint32_t ah[4], al[4];
            uint32_t qaddr = sb + SQ_HI + (uint32_t)(wq * 16 + lrow) * TROWB + kb + lhalf;
            ldsm4(ah[0], ah[1], ah[2], ah[3], qaddr);
            ldsm4(al[0], al[1], al[2], al[3], qaddr + (SQ_LO - SQ_HI));
#pragma unroll
            for (int g = 0; g < 4; g++) {
                uint32_t r0, r1, r2, r3;
                uint32_t kaddr = sb + SK_HI_F + (uint32_t)(g * 16 + lrow) * TROWB + kb + lhalf;
                ldsm4(r0, r1, r2, r3, kaddr);
                uint32_t bh0[2] = {r0, r2}, bh1[2] = {r1, r3};
                ldsm4(r0, r1, r2, r3, kaddr + (SK_LO_F - SK_HI_F));
                uint32_t bl0[2] = {r0, r2}, bl1[2] = {r1, r3};
                mma16816(s[2*g],   ah, bh0); mma16816(s[2*g+1], ah, bh1);
                mma16816(s[2*g],   ah, bl0); mma16816(s[2*g+1], ah, bl1);
                mma16816(s[2*g],   al, bh0); mma16816(s[2*g+1], al, bh1);
            }
        }

        // ---- online softmax ----
        float cA = s[0][0], cB = s[0][2];
#pragma unroll
        for (int ni = 0; ni < 8; ni++) {
            cA = fmaxf(cA, fmaxf(s[ni][0], s[ni][1]));
            cB = fmaxf(cB, fmaxf(s[ni][2], s[ni][3]));
        }
#pragma unroll
        for (int off = 1; off <= 2; off <<= 1) {
            cA = fmaxf(cA, __shfl_xor_sync(0xffffffffu, cA, off));
            cB = fmaxf(cB, __shfl_xor_sync(0xffffffffu, cB, off));
        }
        float nA = fmaxf(mA, cA), nB = fmaxf(mB, cB);
        float scA = __expf(mA - nA), scB = __expf(mB - nB);
        mA = nA; mB = nB;
        float lsA = 0.f, lsB = 0.f;
#pragma unroll
        for (int ni = 0; ni < 8; ni++) {
            s[ni][0] = __expf(s[ni][0] - mA); lsA += s[ni][0];
            s[ni][1] = __expf(s[ni][1] - mA); lsA += s[ni][1];
            s[ni][2] = __expf(s[ni][2] - mB); lsB += s[ni][2];
            s[ni][3] = __expf(s[ni][3] - mB); lsB += s[ni][3];
        }
#pragma unroll
        for (int off = 1; off <= 2; off <<= 1) {
            lsA += __shfl_xor_sync(0xffffffffu, lsA, off);
            lsB += __shfl_xor_sync(0xffffffffu, lsB, off);
        }
        lA = lA * scA + lsA;
        lB = lB * scB + lsB;
#pragma unroll
        for (int di = 0; di < 8; di++) {
            c[di][0] *= scA; c[di][1] *= scA;
            c[di][2] *= scB; c[di][3] *= scB;
        }

        // ---- O += P V ----
#pragma unroll
        for (int ks = 0; ks < 4; ks++) {
            uint32_t pa_hi[4], pa_lo[4];
            split2(s[2*ks][0],   s[2*ks][1],   pa_hi[0], pa_lo[0]);
            split2(s[2*ks][2],   s[2*ks][3],   pa_hi[1], pa_lo[1]);
            split2(s[2*ks+1][0], s[2*ks+1][1], pa_hi[2], pa_lo[2]);
            split2(s[2*ks+1][2], s[2*ks+1][3], pa_hi[3], pa_lo[3]);
#pragma unroll
            for (int g = 0; g < 4; g++) {
                uint32_t r0, r1, r2, r3;
                uint32_t vaddr = sb + SV_HI_F + (uint32_t)(ks * 16 + vrow) * TROWB
                               + (uint32_t)(g * 16 + vcol) * 2;
                ldsm4t(r0, r1, r2, r3, vaddr);
                uint32_t vh0[2] = {r0, r2}, vh1[2] = {r1, r3};
                ldsm4t(r0, r1, r2, r3, vaddr + (SV_LO_F - SV_HI_F));
                uint32_t vl0[2] = {r0, r2}, vl1[2] = {r1, r3};
                mma16816(c[2*g],   pa_hi, vh0); mma16816(c[2*g+1], pa_hi, vh1);
                mma16816(c[2*g],   pa_hi, vl0); mma16816(c[2*g+1], pa_hi, vl1);
                mma16816(c[2*g],   pa_lo, vh0); mma16816(c[2*g+1], pa_lo, vh1);
            }
        }
    }

    // ---- epilogue: context -> fp16 hi/lo split, token-major [T][1024] ----
    const float iA = 1.f / lA, iB = 1.f / lB;
    const int srowA = qb * 128 + wq * 16 + (lane >> 2);
    const size_t baseA = ((size_t)(b * SEQ + srowA)) * DMODEL + h * DKK + (lane & 3) * 2;
    const size_t baseB = baseA + (size_t)8 * DMODEL;
#pragma unroll
    for (int di = 0; di < 8; di++) {
        uint32_t hi, lo;
        split2h(c[di][0] * iA, c[di][1] * iA, hi, lo);
        *reinterpret_cast<uint32_t*>(g_Chi + baseA + di * 8) = hi;
        *reinterpret_cast<uint32_t*>(g_Clo + baseA + di * 8) = lo;
        split2h(c[di][2] * iB, c[di][3] * iB, hi, lo);
        *reinterpret_cast<uint32_t*>(g_Chi + baseB + di * 8) = hi;
        *reinterpret_cast<uint32_t*>(g_Clo + baseB + di * 8) = lo;
    }
}

// ---------------------------------------------------------------------------
extern "C" void kernel_launch(void* const* d_in, const int* in_sizes, int n_in,
                              void* d_out, int out_size)
{
    (void)in_sizes; (void)n_in; (void)out_size;
    const float* x  = (const float*)d_in[0];
    const float* wq = (const float*)d_in[1];
    const float* wk = (const float*)d_in[2];
    const float* wv = (const float*)d_in[3];
    const float* wo = (const float*)d_in[4];
    const float* bo = (const float*)d_in[5];
    float* out = (float*)d_out;

    cudaFuncSetAttribute(qkv_mma_kernel,     cudaFuncAttributeMaxDynamicSharedMemorySize, SM_TOTAL_G);
    cudaFuncSetAttribute(outproj_mma_kernel, cudaFuncAttributeMaxDynamicSharedMemorySize, SM_TOTAL_G);
    cudaFuncSetAttribute(flash_mma_kernel,   cudaFuncAttributeMaxDynamicSharedMemorySize, FSMEM);

    // 0) X -> fp16 hi/lo split; weights -> fp16
    cvt_kernel<<<dim3(4096, 5), 256>>>(x, wq, wk, wv, wo);

    // 1) QKV projections (fp16 2-term HMMA), head-major bf16 outputs
    qkv_mma_kernel<<<dim3(NTOK / 128, DMODEL / 128, 3), 256, SM_TOTAL_G>>>();

    // 2) flash attention (bf16 3-term HMMA), emits fp16-split context
    flash_mma_kernel<<<dim3(SEQ / 128, NBATCH * NHEADS), 256, FSMEM>>>();

    // 3) output projection (fp16 2-term HMMA) + bias
    outproj_mma_kernel<<<dim3(NTOK / 128, DMODEL / 128), 256, SM_TOTAL_G>>>(bo, out);
}